// round 10
// baseline (speedup 1.0000x reference)
#include <cuda_runtime.h>
#include <cuda_bf16.h>
#include <math.h>
#include <stdint.h>

#define TSEQ  4096
#define HID   512
#define NCH   512
#define NHEAD 64
#define NPAIR 256
#define CHUNK 16
#define NCHUNK 256

// ---------------- device scratch ----------------
__device__ __align__(16) __nv_bfloat16 g_W1h[NCH * HID];   // [r][k]
__device__ __align__(16) __nv_bfloat16 g_W1l[NCH * HID];
__device__ __align__(16) __nv_bfloat16 g_Ch[HID * NCH];    // [dd][r]
__device__ __align__(16) __nv_bfloat16 g_Cl[HID * NCH];
__device__ __align__(16) __nv_bfloat16 g_XTh[TSEQ * HID];  // [t][k]
__device__ __align__(16) __nv_bfloat16 g_XTl[TSEQ * HID];
__device__ __align__(16) float g_U[TSEQ * NCH];            // [t][r]
__device__ __align__(16) __nv_bfloat16 g_Yh[TSEQ * NCH];   // [t][r]
__device__ __align__(16) __nv_bfloat16 g_Yl[TSEQ * NCH];
__device__ __align__(16) float g_carryP[NPAIR * NCHUNK * 2];  // [pair][chunk] float2
__device__ __align__(16) float g_prefT[NCHUNK * NPAIR * 2];   // [chunk][pair] inclusive states
__device__ float g_Pm[NHEAD * 64];
__device__ float g_gamma[NHEAD];
__device__ float g_norm[NHEAD];
__device__ float g_pair[NPAIR * 8];   // g, cth, sth, th, g16, c16, s16, pad
__device__ unsigned g_ctr = 0;

// ---------------- helpers ----------------
__device__ __forceinline__ uint32_t smem_u32(const void* p) {
    uint32_t a;
    asm("{ .reg .u64 t; cvta.to.shared.u64 t, %1; cvt.u32.u64 %0, t; }"
        : "=r"(a) : "l"(p));
    return a;
}
__device__ __forceinline__ void cp16(uint32_t s, const void* g) {
    asm volatile("cp.async.cg.shared.global [%0], [%1], 16;" :: "r"(s), "l"(g));
}
__device__ __forceinline__ void cp_commit() { asm volatile("cp.async.commit_group;"); }
__device__ __forceinline__ void cp_wait1()  { asm volatile("cp.async.wait_group 1;"); }
__device__ __forceinline__ void cp_wait0()  { asm volatile("cp.async.wait_group 0;"); }

__device__ __forceinline__ void ldm4(uint32_t* r, uint32_t a) {
    asm volatile("ldmatrix.sync.aligned.m8n8.x4.shared.b16 {%0,%1,%2,%3}, [%4];"
                 : "=r"(r[0]), "=r"(r[1]), "=r"(r[2]), "=r"(r[3]) : "r"(a));
}
__device__ __forceinline__ void mma16816(float* d, const uint32_t* a, const uint32_t* b) {
    asm volatile(
        "mma.sync.aligned.m16n8k16.row.col.f32.bf16.bf16.f32 "
        "{%0,%1,%2,%3}, {%4,%5,%6,%7}, {%8,%9}, {%0,%1,%2,%3};"
        : "+f"(d[0]), "+f"(d[1]), "+f"(d[2]), "+f"(d[3])
        : "r"(a[0]), "r"(a[1]), "r"(a[2]), "r"(a[3]), "r"(b[0]), "r"(b[1]));
}
__device__ __forceinline__ void bf16_split(float x, __nv_bfloat16& h, __nv_bfloat16& l) {
    h = __float2bfloat16_rn(x);
    l = __float2bfloat16_rn(x - __bfloat162float(h));
}
__device__ __forceinline__ float2 ldg64(const float2* p) {
    float2 v;
    asm volatile("ld.global.v2.f32 {%0,%1}, [%2];" : "=f"(v.x), "=f"(v.y) : "l"(p));
    return v;
}

// ============================================================
// setup: per-head expm + norm + pair constants (one block per head)
// ============================================================
__global__ __launch_bounds__(256) void setup(const float* __restrict__ theta_log,
                                             const float* __restrict__ P,
                                             const float* __restrict__ gamma_log,
                                             const float* __restrict__ Bmat) {
    int h = blockIdx.x;
    int t = threadIdx.x;
    bool act = t < 64;
    int i = t >> 3, j = t & 7;
    __shared__ float sA[64], sT[64], sE[64];
    __shared__ float red[256];

    if (act) {
        sA[t] = 0.25f * (P[(h*8 + i)*8 + j] - P[(h*8 + j)*8 + i]);
        float id = (i == j) ? 1.f : 0.f;
        sT[t] = id;
        sE[t] = id;
    }
    __syncthreads();

    for (int k = 1; k <= 12; k++) {
        float s = 0.f;
        if (act) {
#pragma unroll
            for (int l = 0; l < 8; l++) s += sT[i*8 + l] * sA[l*8 + j];
            s *= (1.f / (float)k);
        }
        __syncthreads();
        if (act) { sT[t] = s; sE[t] += s; }
        __syncthreads();
    }
    float s1 = 0.f;
    if (act) {
#pragma unroll
        for (int l = 0; l < 8; l++) s1 += sE[i*8 + l] * sE[l*8 + j];
    }
    __syncthreads();
    if (act) sT[t] = s1;
    __syncthreads();
    if (act) {
        float s2 = 0.f;
#pragma unroll
        for (int l = 0; l < 8; l++) s2 += sT[i*8 + l] * sT[l*8 + j];
        g_Pm[h*64 + t] = s2;
    }

    const float4* bp = (const float4*)(Bmat + h * 8 * HID);
    float acc = 0.f;
#pragma unroll
    for (int e = 0; e < 4; e++) {
        float4 v = bp[t + e * 256];
        acc += v.x*v.x + v.y*v.y + v.z*v.z + v.w*v.w;
    }
    red[t] = acc;
    __syncthreads();
    for (int s = 128; s > 0; s >>= 1) {
        if (t < s) red[t] += red[t + s];
        __syncthreads();
    }

    float g = expf(-expf(gamma_log[h]));
    if (t == 0) {
        g_gamma[h] = g;
        g_norm[h] = sqrtf((1.f - g * g) / red[0]);
    }
    if (t < 4) {
        float g2 = g*g, g4 = g2*g2, g8 = g4*g4, g16 = g8*g8;
        float th = expf(theta_log[h*4 + t]);
        float th16 = 16.f * th;
        int p = h*4 + t;
        g_pair[p*8 + 0] = g;
        g_pair[p*8 + 1] = cosf(th);
        g_pair[p*8 + 2] = sinf(th);
        g_pair[p*8 + 3] = th;
        g_pair[p*8 + 4] = g16;
        g_pair[p*8 + 5] = cosf(th16);
        g_pair[p*8 + 6] = sinf(th16);
        g_pair[p*8 + 7] = 0.f;
    }
}

// ============================================================
// prep: W1 build | Ceff build | X transpose/split  (+ g_ctr reset)
// ============================================================
__global__ __launch_bounds__(256) void prep(const float* __restrict__ Bmat,
                                            const float* __restrict__ Cmat,
                                            const float* __restrict__ X) {
    int b = blockIdx.x;
    int tid = threadIdx.x;

    if (b == 0 && tid == 0) g_ctr = 0;

    if (b < 256) {
        int q = b * 256 + tid;
        int r = q >> 7;
        int d4 = (q & 127) << 2;
        int h = r >> 3, N = r & 7;
        const float* pm = &g_Pm[h*64 + N*8];
        float4 a = make_float4(0.f, 0.f, 0.f, 0.f);
#pragma unroll
        for (int n = 0; n < 8; n++) {
            float4 bv = *(const float4*)&Bmat[(size_t)(h*8 + n) * HID + d4];
            float w = pm[n];
            a.x = fmaf(w, bv.x, a.x); a.y = fmaf(w, bv.y, a.y);
            a.z = fmaf(w, bv.z, a.z); a.w = fmaf(w, bv.w, a.w);
        }
        float nm = g_norm[h];
        float v[4] = {a.x*nm, a.y*nm, a.z*nm, a.w*nm};
        __nv_bfloat16 hh[4], ll[4];
#pragma unroll
        for (int e = 0; e < 4; e++) bf16_split(v[e], hh[e], ll[e]);
        *(__nv_bfloat162*)&g_W1h[r*HID + d4]     = __nv_bfloat162(hh[0], hh[1]);
        *(__nv_bfloat162*)&g_W1h[r*HID + d4 + 2] = __nv_bfloat162(hh[2], hh[3]);
        *(__nv_bfloat162*)&g_W1l[r*HID + d4]     = __nv_bfloat162(ll[0], ll[1]);
        *(__nv_bfloat162*)&g_W1l[r*HID + d4 + 2] = __nv_bfloat162(ll[2], ll[3]);
    } else if (b < 512) {
        int q = (b - 256) * 256 + tid;
        int dd = q >> 7;
        int c4 = (q & 127) << 2;
        int h = c4 >> 3;
        float cm[8];
        *(float4*)&cm[0] = *(const float4*)&Cmat[(size_t)dd * NCH + h*8];
        *(float4*)&cm[4] = *(const float4*)&Cmat[(size_t)dd * NCH + h*8 + 4];
        __nv_bfloat16 hh[4], ll[4];
#pragma unroll
        for (int e = 0; e < 4; e++) {
            int N = (c4 + e) & 7;
            const float* pm = &g_Pm[h*64 + N*8];
            float s = 0.f;
#pragma unroll
            for (int n = 0; n < 8; n++) s = fmaf(cm[n], pm[n], s);
            bf16_split(s, hh[e], ll[e]);
        }
        *(__nv_bfloat162*)&g_Ch[dd*NCH + c4]     = __nv_bfloat162(hh[0], hh[1]);
        *(__nv_bfloat162*)&g_Ch[dd*NCH + c4 + 2] = __nv_bfloat162(hh[2], hh[3]);
        *(__nv_bfloat162*)&g_Cl[dd*NCH + c4]     = __nv_bfloat162(ll[0], ll[1]);
        *(__nv_bfloat162*)&g_Cl[dd*NCH + c4 + 2] = __nv_bfloat162(ll[2], ll[3]);
    } else {
        __shared__ float t32[32][33];
        int b2 = b - 512;
        int tb = b2 & 127;
        int kb = b2 >> 7;
        int tx = tid & 31, ty = tid >> 5;
#pragma unroll
        for (int i = 0; i < 4; i++)
            t32[ty + 8*i][tx] = X[(size_t)(kb*32 + ty + 8*i) * TSEQ + tb*32 + tx];
        __syncthreads();
#pragma unroll
        for (int i = 0; i < 4; i++) {
            float v = t32[tx][ty + 8*i];
            __nv_bfloat16 hi, lo; bf16_split(v, hi, lo);
            size_t o = (size_t)(tb*32 + ty + 8*i) * HID + kb*32 + tx;
            g_XTh[o] = hi;
            g_XTl[o] = lo;
        }
    }
}

// ============================================================
// bf16 3-MMA split GEMM, 3-stage cp.async, one sync per k-iter.
// MODE 0: write g_U + per-chunk carries; LAST block also runs the
//         carry scan (inclusive states -> g_prefT[chunk][pair]).
// MODE 1: direct stores + D*x from bf16 splits
// ============================================================
#define PITCHB 80
#define ARRB   (128*PITCHB)   // 10240
#define STAGEB (4*ARRB)       // 40960
#define NSTAGE 3
#define PITCHF 136

template <int MODE>
__global__ __launch_bounds__(256, 1)
void gemm_mma(const __nv_bfloat16* __restrict__ Ah, const __nv_bfloat16* __restrict__ Al,
              const __nv_bfloat16* __restrict__ Bh, const __nv_bfloat16* __restrict__ Bl,
              float* __restrict__ Cout,
              const __nv_bfloat16* __restrict__ Xh, const __nv_bfloat16* __restrict__ Xl,
              const float* __restrict__ Dv) {
    extern __shared__ char smem[];
    uint32_t sb = smem_u32(smem);
    int tid = threadIdx.x, lane = tid & 31, wid = tid >> 5;
    int m0 = blockIdx.x * 128, n0 = blockIdx.y * 128;
    int m_w = (wid & 1) * 64, n_w = (wid >> 1) * 32;

    const __nv_bfloat16* gp[4] = {Ah, Al, Bh, Bl};

    auto load_stage = [&](int s, int k0) {
        uint32_t base = sb + s * STAGEB;
#pragma unroll
        for (int a = 0; a < 4; a++) {
            int row0 = (a < 2) ? m0 : n0;
#pragma unroll
            for (int e = 0; e < 2; e++) {
                int idx = tid + e * 256;
                int row = idx >> 2, q = idx & 3;
                cp16(base + a * ARRB + row * PITCHB + q * 16,
                     gp[a] + (size_t)(row0 + row) * 512 + k0 + q * 8);
            }
        }
    };

    float acc[4][4][4];
#pragma unroll
    for (int i = 0; i < 4; i++)
#pragma unroll
        for (int j = 0; j < 4; j++)
#pragma unroll
            for (int q = 0; q < 4; q++) acc[i][j][q] = 0.f;

    load_stage(0, 0);  cp_commit();
    load_stage(1, 32); cp_commit();

#pragma unroll 1
    for (int kt = 0; kt < 16; kt++) {
        if (kt < 15) cp_wait1(); else cp_wait0();
        __syncthreads();
        if (kt + 2 < 16) {
            load_stage((kt + 2) % NSTAGE, (kt + 2) * 32);
            cp_commit();
        }
        uint32_t base = sb + (kt % NSTAGE) * STAGEB;
#pragma unroll
        for (int kk = 0; kk < 2; kk++) {
            int cb = kk * 32;
            uint32_t ah[4][4], al[4][4], bh[2][4], bl[2][4];
#pragma unroll
            for (int i = 0; i < 4; i++) {
                int row = m_w + 16*i + (lane & 15);
                uint32_t ad = base + row * PITCHB + cb + 16 * (lane >> 4);
                ldm4(ah[i], ad);
                ldm4(al[i], ad + ARRB);
            }
#pragma unroll
            for (int j2 = 0; j2 < 2; j2++) {
                int n = n_w + 16*j2 + (lane & 7) + 8 * (lane >> 4);
                uint32_t ad = base + 2 * ARRB + n * PITCHB + cb + 16 * ((lane >> 3) & 1);
                ldm4(bh[j2], ad);
                ldm4(bl[j2], ad + ARRB);
            }
#pragma unroll
            for (int i = 0; i < 4; i++)
#pragma unroll
                for (int j = 0; j < 4; j++) {
                    const uint32_t* Bp_h = &bh[j >> 1][(j & 1) * 2];
                    const uint32_t* Bp_l = &bl[j >> 1][(j & 1) * 2];
                    mma16816(acc[i][j], ah[i], Bp_h);
                    mma16816(acc[i][j], ah[i], Bp_l);
                    mma16816(acc[i][j], al[i], Bp_h);
                }
        }
    }

    int rh = lane >> 2, c2 = (lane & 3) * 2;

    if (MODE == 1) {
        float dvx[4], dvy[4];
#pragma unroll
        for (int j = 0; j < 4; j++) {
            int col = n0 + n_w + 8*j + c2;
            dvx[j] = Dv[col];
            dvy[j] = Dv[col + 1];
        }
#pragma unroll
        for (int i = 0; i < 4; i++) {
            int row = m0 + m_w + 16*i + rh;
#pragma unroll
            for (int j = 0; j < 4; j++) {
                int col = n0 + n_w + 8*j + c2;
                size_t o0 = (size_t)row * 512 + col;
                size_t o1 = (size_t)(row + 8) * 512 + col;
                __nv_bfloat162 xh0 = *(const __nv_bfloat162*)&Xh[o0];
                __nv_bfloat162 xl0 = *(const __nv_bfloat162*)&Xl[o0];
                __nv_bfloat162 xh1 = *(const __nv_bfloat162*)&Xh[o1];
                __nv_bfloat162 xl1 = *(const __nv_bfloat162*)&Xl[o1];
                float x00 = __bfloat162float(xh0.x) + __bfloat162float(xl0.x);
                float x01 = __bfloat162float(xh0.y) + __bfloat162float(xl0.y);
                float x10 = __bfloat162float(xh1.x) + __bfloat162float(xl1.x);
                float x11 = __bfloat162float(xh1.y) + __bfloat162float(xl1.y);
                *(float2*)&Cout[o0] = make_float2(fmaf(dvx[j], x00, acc[i][j][0]),
                                                  fmaf(dvy[j], x01, acc[i][j][1]));
                *(float2*)&Cout[o1] = make_float2(fmaf(dvx[j], x10, acc[i][j][2]),
                                                  fmaf(dvy[j], x11, acc[i][j][3]));
            }
        }
        return;
    }

    // ---------------- MODE 0 epilogue ----------------
    __syncthreads();
    float* Us = (float*)smem;   // [128][PITCHF]
#pragma unroll
    for (int i = 0; i < 4; i++) {
        int row = m_w + 16*i + rh;
#pragma unroll
        for (int j = 0; j < 4; j++) {
            int col = n_w + 8*j + c2;
            *(float2*)&Us[row * PITCHF + col]       = make_float2(acc[i][j][0], acc[i][j][1]);
            *(float2*)&Us[(row + 8) * PITCHF + col] = make_float2(acc[i][j][2], acc[i][j][3]);
        }
    }
    __syncthreads();

#pragma unroll
    for (int e = 0; e < 16; e++) {
        int idx = tid + e * 256;
        int t = idx >> 5, c4 = (idx & 31) << 2;
        float4 v = *(float4*)&Us[t * PITCHF + c4];
        *(float4*)&Cout[(size_t)(m0 + t) * 512 + n0 + c4] = v;
    }

    // per-chunk carries: 8 chunks of 16 rows, 512 units over 256 threads
#pragma unroll
    for (int u0 = 0; u0 < 2; u0++) {
        int u = tid + u0 * 256;
        int pl = u & 63, ch = u >> 6;          // pair-in-tile, chunk 0..7
        int P = (n0 >> 1) + pl;
        float g  = g_pair[P*8 + 0];
        float gc = g * g_pair[P*8 + 1];
        float gs = g * g_pair[P*8 + 2];
        float a = 0.f, bb = 0.f;
        const float* src = &Us[(ch * 16) * PITCHF + 2 * pl];
#pragma unroll
        for (int i = 0; i < 16; i++) {
            float2 uu = *(const float2*)(src + i * PITCHF);
            float na = fmaf(gc, a, fmaf(-gs, bb, uu.x));
            float nb = fmaf(gs, a, fmaf( gc, bb, uu.y));
            a = na; bb = nb;
        }
        int C = (blockIdx.x << 3) + ch;
        *(float2*)&g_carryP[(P * NCHUNK + C) * 2] = make_float2(a, bb);
    }

    // ---------------- last-block carry scan (replaces kscan kernel) ----------------
    __shared__ unsigned s_last;
    __threadfence();
    __syncthreads();
    if (tid == 0) {
        unsigned old = atomicAdd(&g_ctr, 1u);
        s_last = (old == 127u) ? 1u : 0u;
    }
    __syncthreads();
    if (s_last) {
        __threadfence();   // acquire side: see all blocks' carry stores
        int p = tid;       // thread = pair
        float gl = g_pair[p*8 + 4];
        float Mx = gl * g_pair[p*8 + 5];
        float My = gl * g_pair[p*8 + 6];
        const float2* cr = (const float2*)g_carryP + p * NCHUNK;
        float2* pr = (float2*)g_prefT;
        float a = 0.f, b = 0.f;
        float2 cb2[8];
#pragma unroll 1
        for (int base = 0; base < NCHUNK; base += 8) {
#pragma unroll
            for (int e = 0; e < 8; e++) cb2[e] = ldg64(cr + base + e);
#pragma unroll
            for (int e = 0; e < 8; e++) {
                float na = fmaf(Mx, a, fmaf(-My, b, cb2[e].x));
                float nb = fmaf(Mx, b, fmaf( My, a, cb2[e].y));
                a = na; b = nb;
                pr[(base + e) * NPAIR + p] = make_float2(a, b);   // coalesced
            }
        }
    }
}

// ============================================================
// scan3: block c handles rows [c*16, c*16+16); thread p = pair.
// Seed = inclusive state of chunk c-1 (coalesced), no chain.
// ============================================================
__global__ __launch_bounds__(256, 1) void scan3() {
    int c = blockIdx.x;        // 0..255
    int p = threadIdx.x;       // 0..255

    float g  = g_pair[p*8 + 0];
    float gc = g * g_pair[p*8 + 1];
    float gs = g * g_pair[p*8 + 2];

    float a = 0.f, b = 0.f;
    if (c > 0) {
        float2 s = ldg64((const float2*)g_prefT + (c - 1) * NPAIR + p);
        a = s.x; b = s.y;
    }

    const float2* up = (const float2*)(g_U + (size_t)(c * CHUNK) * NCH) + p;
    __nv_bfloat162* yh = (__nv_bfloat162*)(g_Yh + (size_t)(c * CHUNK) * NCH) + p;
    __nv_bfloat162* yl = (__nv_bfloat162*)(g_Yl + (size_t)(c * CHUNK) * NCH) + p;

    float2 ub[8];
#pragma unroll
    for (int base = 0; base < CHUNK; base += 8) {
#pragma unroll
        for (int e = 0; e < 8; e++) ub[e] = ldg64(up + (base + e) * 256);
#pragma unroll
        for (int e = 0; e < 8; e++) {
            float na = fmaf(gc, a, fmaf(-gs, b, ub[e].x));
            float nb = fmaf(gs, a, fmaf( gc, b, ub[e].y));
            a = na; b = nb;
            __nv_bfloat16 ha, la, hb, lb;
            bf16_split(a, ha, la);
            bf16_split(b, hb, lb);
            yh[(base + e) * 256] = __nv_bfloat162(ha, hb);
            yl[(base + e) * 256] = __nv_bfloat162(la, lb);
        }
    }
}

// ============================================================
extern "C" void kernel_launch(void* const* d_in, const int* in_sizes, int n_in,
                              void* d_out, int out_size) {
    const float* X         = (const float*)d_in[0];
    const float* theta_log = (const float*)d_in[1];
    const float* P         = (const float*)d_in[2];
    const float* Bmat      = (const float*)d_in[3];
    const float* Cmat      = (const float*)d_in[4];
    const float* Dv        = (const float*)d_in[5];
    const float* gamma_log = (const float*)d_in[6];
    float* out = (float*)d_out;

    const int GEMM_SMEM = NSTAGE * STAGEB;   // 122880
    cudaFuncSetAttribute(gemm_mma<0>, cudaFuncAttributeMaxDynamicSharedMemorySize, GEMM_SMEM);
    cudaFuncSetAttribute(gemm_mma<1>, cudaFuncAttributeMaxDynamicSharedMemorySize, GEMM_SMEM);

    setup<<<NHEAD, 256>>>(theta_log, P, gamma_log, Bmat);
    prep<<<2560, 256>>>(Bmat, Cmat, X);

    float* U;   cudaGetSymbolAddress((void**)&U, g_U);
    __nv_bfloat16 *XTh, *XTl, *W1h, *W1l, *Yh, *Yl, *Ch, *Cl;
    cudaGetSymbolAddress((void**)&XTh, g_XTh);
    cudaGetSymbolAddress((void**)&XTl, g_XTl);
    cudaGetSymbolAddress((void**)&W1h, g_W1h);
    cudaGetSymbolAddress((void**)&W1l, g_W1l);
    cudaGetSymbolAddress((void**)&Yh, g_Yh);
    cudaGetSymbolAddress((void**)&Yl, g_Yl);
    cudaGetSymbolAddress((void**)&Ch, g_Ch);
    cudaGetSymbolAddress((void**)&Cl, g_Cl);

    dim3 gg(TSEQ / 128, NCH / 128);   // (32, 4)
    gemm_mma<0><<<gg, 256, GEMM_SMEM>>>(XTh, XTl, W1h, W1l, U, nullptr, nullptr, nullptr);
    scan3<<<NCHUNK, 256>>>();
    gemm_mma<1><<<gg, 256, GEMM_SMEM>>>(Yh, Yl, Ch, Cl, out, XTh, XTl, Dv);
}

// round 11
// speedup vs baseline: 1.6171x; 1.6171x over previous
#include <cuda_runtime.h>
#include <cuda_bf16.h>
#include <math.h>
#include <stdint.h>

#define TSEQ  4096
#define HID   512
#define NCH   512
#define NHEAD 64
#define NPAIR 256
#define CHUNK 16
#define NCHUNK 256

// ---------------- device scratch ----------------
__device__ __align__(16) __nv_bfloat16 g_W1h[NCH * HID];   // [r][k]
__device__ __align__(16) __nv_bfloat16 g_W1l[NCH * HID];
__device__ __align__(16) __nv_bfloat16 g_Ch[HID * NCH];    // [dd][r]
__device__ __align__(16) __nv_bfloat16 g_Cl[HID * NCH];
__device__ __align__(16) __nv_bfloat16 g_XTh[TSEQ * HID];  // [t][k]
__device__ __align__(16) __nv_bfloat16 g_XTl[TSEQ * HID];
__device__ __align__(16) float g_U[TSEQ * NCH];            // [t][r]
__device__ __align__(16) __nv_bfloat16 g_Yh[TSEQ * NCH];   // [t][r]
__device__ __align__(16) __nv_bfloat16 g_Yl[TSEQ * NCH];
__device__ __align__(16) float g_carryP[NPAIR * NCHUNK * 2];  // [pair][chunk] float2
__device__ __align__(16) float g_prefT[NCHUNK * NPAIR * 2];   // [chunk][pair] inclusive states
__device__ float g_pair[NPAIR * 8];   // g, cth, sth, th, g16, c16, s16, pad

// ---------------- helpers ----------------
__device__ __forceinline__ uint32_t smem_u32(const void* p) {
    uint32_t a;
    asm("{ .reg .u64 t; cvta.to.shared.u64 t, %1; cvt.u32.u64 %0, t; }"
        : "=r"(a) : "l"(p));
    return a;
}
__device__ __forceinline__ void cp16(uint32_t s, const void* g) {
    asm volatile("cp.async.cg.shared.global [%0], [%1], 16;" :: "r"(s), "l"(g));
}
__device__ __forceinline__ void cp_commit() { asm volatile("cp.async.commit_group;"); }
__device__ __forceinline__ void cp_wait2()  { asm volatile("cp.async.wait_group 2;"); }
__device__ __forceinline__ void cp_wait1()  { asm volatile("cp.async.wait_group 1;"); }
__device__ __forceinline__ void cp_wait0()  { asm volatile("cp.async.wait_group 0;"); }

__device__ __forceinline__ void ldm4(uint32_t* r, uint32_t a) {
    asm volatile("ldmatrix.sync.aligned.m8n8.x4.shared.b16 {%0,%1,%2,%3}, [%4];"
                 : "=r"(r[0]), "=r"(r[1]), "=r"(r[2]), "=r"(r[3]) : "r"(a));
}
__device__ __forceinline__ void mma16816(float* d, const uint32_t* a, const uint32_t* b) {
    asm volatile(
        "mma.sync.aligned.m16n8k16.row.col.f32.bf16.bf16.f32 "
        "{%0,%1,%2,%3}, {%4,%5,%6,%7}, {%8,%9}, {%0,%1,%2,%3};"
        : "+f"(d[0]), "+f"(d[1]), "+f"(d[2]), "+f"(d[3])
        : "r"(a[0]), "r"(a[1]), "r"(a[2]), "r"(a[3]), "r"(b[0]), "r"(b[1]));
}
__device__ __forceinline__ void bf16_split(float x, __nv_bfloat16& h, __nv_bfloat16& l) {
    h = __float2bfloat16_rn(x);
    l = __float2bfloat16_rn(x - __bfloat162float(h));
}
__device__ __forceinline__ float2 ldg64(const float2* p) {
    float2 v;
    asm volatile("ld.global.v2.f32 {%0,%1}, [%2];" : "=f"(v.x), "=f"(v.y) : "l"(p));
    return v;
}
__device__ __forceinline__ float2 cmul(float2 a, float2 b) {
    return make_float2(a.x*b.x - a.y*b.y, a.x*b.y + a.y*b.x);
}

// ============================================================
// setup: per-head expm + norm + pair constants + W1 + Ceff
// (one block of 256 threads per head; Pm kept in smem)
// ============================================================
__global__ __launch_bounds__(256) void setup(const float* __restrict__ theta_log,
                                             const float* __restrict__ P,
                                             const float* __restrict__ gamma_log,
                                             const float* __restrict__ Bmat,
                                             const float* __restrict__ Cmat) {
    int h = blockIdx.x;
    int t = threadIdx.x;
    bool act = t < 64;
    int i = t >> 3, j = t & 7;
    __shared__ float sA[64], sT[64], sE[64];
    __shared__ float red[256];

    if (act) {
        sA[t] = 0.25f * (P[(h*8 + i)*8 + j] - P[(h*8 + j)*8 + i]);
        float id = (i == j) ? 1.f : 0.f;
        sT[t] = id;
        sE[t] = id;
    }
    __syncthreads();

    for (int k = 1; k <= 12; k++) {
        float s = 0.f;
        if (act) {
#pragma unroll
            for (int l = 0; l < 8; l++) s += sT[i*8 + l] * sA[l*8 + j];
            s *= (1.f / (float)k);
        }
        __syncthreads();
        if (act) { sT[t] = s; sE[t] += s; }
        __syncthreads();
    }
    float s1 = 0.f;
    if (act) {
#pragma unroll
        for (int l = 0; l < 8; l++) s1 += sE[i*8 + l] * sE[l*8 + j];
    }
    __syncthreads();
    if (act) sT[t] = s1;
    __syncthreads();
    float s2 = 0.f;
    if (act) {
#pragma unroll
        for (int l = 0; l < 8; l++) s2 += sT[i*8 + l] * sT[l*8 + j];
    }
    __syncthreads();
    if (act) sA[t] = s2;      // sA = final Pm for this head

    // norm reduction: sum of squares of Bmat rows for this head
    const float4* bp = (const float4*)(Bmat + h * 8 * HID);
    float acc = 0.f;
#pragma unroll
    for (int e = 0; e < 4; e++) {
        float4 v = bp[t + e * 256];
        acc += v.x*v.x + v.y*v.y + v.z*v.z + v.w*v.w;
    }
    red[t] = acc;
    __syncthreads();
    for (int s = 128; s > 0; s >>= 1) {
        if (t < s) red[t] += red[t + s];
        __syncthreads();
    }

    float g = expf(-expf(gamma_log[h]));
    float nrm = sqrtf((1.f - g * g) / red[0]);

    if (t < 4) {
        float g2 = g*g, g4 = g2*g2, g8 = g4*g4, g16 = g8*g8;
        float th = expf(theta_log[h*4 + t]);
        float th16 = 16.f * th;
        int p = h*4 + t;
        g_pair[p*8 + 0] = g;
        g_pair[p*8 + 1] = cosf(th);
        g_pair[p*8 + 2] = sinf(th);
        g_pair[p*8 + 3] = th;
        g_pair[p*8 + 4] = g16;
        g_pair[p*8 + 5] = cosf(th16);
        g_pair[p*8 + 6] = sinf(th16);
        g_pair[p*8 + 7] = 0.f;
    }

    // ---- W1 rows for this head: r = h*8+N, 1024 float4 units ----
#pragma unroll
    for (int e = 0; e < 4; e++) {
        int q = t + e * 256;           // 0..1023
        int N = q >> 7;                // 0..7
        int d4 = (q & 127) << 2;
        const float* pm = &sA[N*8];
        float4 a = make_float4(0.f, 0.f, 0.f, 0.f);
#pragma unroll
        for (int n = 0; n < 8; n++) {
            float4 bv = *(const float4*)&Bmat[(size_t)(h*8 + n) * HID + d4];
            float w = pm[n];
            a.x = fmaf(w, bv.x, a.x); a.y = fmaf(w, bv.y, a.y);
            a.z = fmaf(w, bv.z, a.z); a.w = fmaf(w, bv.w, a.w);
        }
        float v[4] = {a.x*nrm, a.y*nrm, a.z*nrm, a.w*nrm};
        __nv_bfloat16 hh[4], ll[4];
#pragma unroll
        for (int k = 0; k < 4; k++) bf16_split(v[k], hh[k], ll[k]);
        int r = h*8 + N;
        *(__nv_bfloat162*)&g_W1h[r*HID + d4]     = __nv_bfloat162(hh[0], hh[1]);
        *(__nv_bfloat162*)&g_W1h[r*HID + d4 + 2] = __nv_bfloat162(hh[2], hh[3]);
        *(__nv_bfloat162*)&g_W1l[r*HID + d4]     = __nv_bfloat162(ll[0], ll[1]);
        *(__nv_bfloat162*)&g_W1l[r*HID + d4 + 2] = __nv_bfloat162(ll[2], ll[3]);
    }

    // ---- Ceff columns for this head: c = h*8+N, all 512 dd ----
#pragma unroll
    for (int e = 0; e < 16; e++) {
        int q = t + e * 256;           // 0..4095
        int dd = q >> 3;
        int N = q & 7;
        const float* pm = &sA[N*8];
        float4 c0 = *(const float4*)&Cmat[(size_t)dd * NCH + h*8];
        float4 c1 = *(const float4*)&Cmat[(size_t)dd * NCH + h*8 + 4];
        float s = pm[0]*c0.x + pm[1]*c0.y + pm[2]*c0.z + pm[3]*c0.w
                + pm[4]*c1.x + pm[5]*c1.y + pm[6]*c1.z + pm[7]*c1.w;
        __nv_bfloat16 hh, ll;
        bf16_split(s, hh, ll);
        g_Ch[(size_t)dd * NCH + h*8 + N] = hh;
        g_Cl[(size_t)dd * NCH + h*8 + N] = ll;
    }
}

// ============================================================
// prep: X transpose/split only (2048 blocks)
// ============================================================
__global__ __launch_bounds__(256) void prep(const float* __restrict__ X) {
    __shared__ float t32[32][33];
    int b = blockIdx.x;
    int tid = threadIdx.x;
    int tb = b & 127;
    int kb = b >> 7;
    int tx = tid & 31, ty = tid >> 5;
#pragma unroll
    for (int i = 0; i < 4; i++)
        t32[ty + 8*i][tx] = X[(size_t)(kb*32 + ty + 8*i) * TSEQ + tb*32 + tx];
    __syncthreads();
#pragma unroll
    for (int i = 0; i < 4; i++) {
        float v = t32[tx][ty + 8*i];
        __nv_bfloat16 hi, lo; bf16_split(v, hi, lo);
        size_t o = (size_t)(tb*32 + ty + 8*i) * HID + kb*32 + tx;
        g_XTh[o] = hi;
        g_XTl[o] = lo;
    }
}

// ============================================================
// bf16 3-MMA split GEMM, 4-stage cp.async, one sync per k-iter.
// MODE 0: write g_U + per-chunk carries (8 chunks of 16 rows)
// MODE 1: direct stores + D*x from bf16 splits
// ============================================================
#define PITCHB 80
#define ARRB   (128*PITCHB)   // 10240
#define STAGEB (4*ARRB)       // 40960
#define NSTAGE 4
#define PITCHF 136

template <int MODE>
__global__ __launch_bounds__(256, 1)
void gemm_mma(const __nv_bfloat16* __restrict__ Ah, const __nv_bfloat16* __restrict__ Al,
              const __nv_bfloat16* __restrict__ Bh, const __nv_bfloat16* __restrict__ Bl,
              float* __restrict__ Cout,
              const __nv_bfloat16* __restrict__ Xh, const __nv_bfloat16* __restrict__ Xl,
              const float* __restrict__ Dv) {
    extern __shared__ char smem[];
    uint32_t sb = smem_u32(smem);
    int tid = threadIdx.x, lane = tid & 31, wid = tid >> 5;
    int m0 = blockIdx.x * 128, n0 = blockIdx.y * 128;
    int m_w = (wid & 1) * 64, n_w = (wid >> 1) * 32;

    const __nv_bfloat16* gp[4] = {Ah, Al, Bh, Bl};

    auto load_stage = [&](int s, int k0) {
        uint32_t base = sb + s * STAGEB;
#pragma unroll
        for (int a = 0; a < 4; a++) {
            int row0 = (a < 2) ? m0 : n0;
#pragma unroll
            for (int e = 0; e < 2; e++) {
                int idx = tid + e * 256;
                int row = idx >> 2, q = idx & 3;
                cp16(base + a * ARRB + row * PITCHB + q * 16,
                     gp[a] + (size_t)(row0 + row) * 512 + k0 + q * 8);
            }
        }
    };

    float acc[4][4][4];
#pragma unroll
    for (int i = 0; i < 4; i++)
#pragma unroll
        for (int j = 0; j < 4; j++)
#pragma unroll
            for (int q = 0; q < 4; q++) acc[i][j][q] = 0.f;

    load_stage(0, 0);  cp_commit();
    load_stage(1, 32); cp_commit();
    load_stage(2, 64); cp_commit();

#pragma unroll 1
    for (int kt = 0; kt < 16; kt++) {
        if (kt <= 13) cp_wait2();
        else if (kt == 14) cp_wait1();
        else cp_wait0();
        __syncthreads();
        if (kt + 3 < 16) {
            load_stage((kt + 3) & 3, (kt + 3) * 32);
            cp_commit();
        }
        uint32_t base = sb + (kt & 3) * STAGEB;
#pragma unroll
        for (int kk = 0; kk < 2; kk++) {
            int cb = kk * 32;
            uint32_t ah[4][4], al[4][4], bh[2][4], bl[2][4];
#pragma unroll
            for (int i = 0; i < 4; i++) {
                int row = m_w + 16*i + (lane & 15);
                uint32_t ad = base + row * PITCHB + cb + 16 * (lane >> 4);
                ldm4(ah[i], ad);
                ldm4(al[i], ad + ARRB);
            }
#pragma unroll
            for (int j2 = 0; j2 < 2; j2++) {
                int n = n_w + 16*j2 + (lane & 7) + 8 * (lane >> 4);
                uint32_t ad = base + 2 * ARRB + n * PITCHB + cb + 16 * ((lane >> 3) & 1);
                ldm4(bh[j2], ad);
                ldm4(bl[j2], ad + ARRB);
            }
#pragma unroll
            for (int i = 0; i < 4; i++)
#pragma unroll
                for (int j = 0; j < 4; j++) {
                    const uint32_t* Bp_h = &bh[j >> 1][(j & 1) * 2];
                    const uint32_t* Bp_l = &bl[j >> 1][(j & 1) * 2];
                    mma16816(acc[i][j], ah[i], Bp_h);
                    mma16816(acc[i][j], ah[i], Bp_l);
                    mma16816(acc[i][j], al[i], Bp_h);
                }
        }
    }

    int rh = lane >> 2, c2 = (lane & 3) * 2;

    if (MODE == 1) {
        float dvx[4], dvy[4];
#pragma unroll
        for (int j = 0; j < 4; j++) {
            int col = n0 + n_w + 8*j + c2;
            dvx[j] = Dv[col];
            dvy[j] = Dv[col + 1];
        }
#pragma unroll
        for (int i = 0; i < 4; i++) {
            int row = m0 + m_w + 16*i + rh;
#pragma unroll
            for (int j = 0; j < 4; j++) {
                int col = n0 + n_w + 8*j + c2;
                size_t o0 = (size_t)row * 512 + col;
                size_t o1 = (size_t)(row + 8) * 512 + col;
                __nv_bfloat162 xh0 = *(const __nv_bfloat162*)&Xh[o0];
                __nv_bfloat162 xl0 = *(const __nv_bfloat162*)&Xl[o0];
                __nv_bfloat162 xh1 = *(const __nv_bfloat162*)&Xh[o1];
                __nv_bfloat162 xl1 = *(const __nv_bfloat162*)&Xl[o1];
                float x00 = __bfloat162float(xh0.x) + __bfloat162float(xl0.x);
                float x01 = __bfloat162float(xh0.y) + __bfloat162float(xl0.y);
                float x10 = __bfloat162float(xh1.x) + __bfloat162float(xl1.x);
                float x11 = __bfloat162float(xh1.y) + __bfloat162float(xl1.y);
                *(float2*)&Cout[o0] = make_float2(fmaf(dvx[j], x00, acc[i][j][0]),
                                                  fmaf(dvy[j], x01, acc[i][j][1]));
                *(float2*)&Cout[o1] = make_float2(fmaf(dvx[j], x10, acc[i][j][2]),
                                                  fmaf(dvy[j], x11, acc[i][j][3]));
            }
        }
        return;
    }

    // ---------------- MODE 0 epilogue ----------------
    __syncthreads();
    float* Us = (float*)smem;   // [128][PITCHF]
#pragma unroll
    for (int i = 0; i < 4; i++) {
        int row = m_w + 16*i + rh;
#pragma unroll
        for (int j = 0; j < 4; j++) {
            int col = n_w + 8*j + c2;
            *(float2*)&Us[row * PITCHF + col]       = make_float2(acc[i][j][0], acc[i][j][1]);
            *(float2*)&Us[(row + 8) * PITCHF + col] = make_float2(acc[i][j][2], acc[i][j][3]);
        }
    }
    __syncthreads();

#pragma unroll
    for (int e = 0; e < 16; e++) {
        int idx = tid + e * 256;
        int t = idx >> 5, c4 = (idx & 31) << 2;
        float4 v = *(float4*)&Us[t * PITCHF + c4];
        *(float4*)&Cout[(size_t)(m0 + t) * 512 + n0 + c4] = v;
    }

    // per-chunk carries: 8 chunks of 16 rows, 512 units over 256 threads
#pragma unroll
    for (int u0 = 0; u0 < 2; u0++) {
        int u = tid + u0 * 256;
        int pl = u & 63, ch = u >> 6;          // pair-in-tile, chunk 0..7
        int P = (n0 >> 1) + pl;
        float g  = g_pair[P*8 + 0];
        float gc = g * g_pair[P*8 + 1];
        float gs = g * g_pair[P*8 + 2];
        float a = 0.f, bb = 0.f;
        const float* src = &Us[(ch * 16) * PITCHF + 2 * pl];
#pragma unroll
        for (int i = 0; i < 16; i++) {
            float2 uu = *(const float2*)(src + i * PITCHF);
            float na = fmaf(gc, a, fmaf(-gs, bb, uu.x));
            float nb = fmaf(gs, a, fmaf( gc, bb, uu.y));
            a = na; bb = nb;
        }
        int C = (blockIdx.x << 3) + ch;
        *(float2*)&g_carryP[(P * NCHUNK + C) * 2] = make_float2(a, bb);
    }
}

// ============================================================
// kscan: warp-level two-level scan over 256 chunk carries per pair.
// 64 blocks x 128 threads; warp = one pair; lane holds 8 chunks.
// ============================================================
__global__ __launch_bounds__(128, 1) void kscan() {
    int wid = threadIdx.x >> 5, lane = threadIdx.x & 31;
    int p = blockIdx.x * 4 + wid;

    float gl = g_pair[p*8 + 4];
    float2 M = make_float2(gl * g_pair[p*8 + 5], gl * g_pair[p*8 + 6]);

    float2 cb[8];
    const float2* cr = (const float2*)g_carryP + p * NCHUNK + lane * 8;
#pragma unroll
    for (int e = 0; e < 8; e++) cb[e] = ldg64(cr + e);

    float2 s = cb[0];
#pragma unroll
    for (int e = 1; e < 8; e++) {
        s = make_float2(fmaf(M.x, s.x, fmaf(-M.y, s.y, cb[e].x)),
                        fmaf(M.x, s.y, fmaf( M.y, s.x, cb[e].y)));
    }

    float2 A = cmul(M, M);
    A = cmul(A, A);
    A = cmul(A, A);   // M^8

    float2 x = s;
#pragma unroll
    for (int st = 1; st < 32; st <<= 1) {
        float px = __shfl_up_sync(0xFFFFFFFF, x.x, st);
        float py = __shfl_up_sync(0xFFFFFFFF, x.y, st);
        if (lane >= st) {
            x.x = fmaf(A.x, px, fmaf(-A.y, py, x.x));
            x.y = fmaf(A.x, py, fmaf( A.y, px, x.y));
        }
        A = cmul(A, A);
    }

    float sx = __shfl_up_sync(0xFFFFFFFF, x.x, 1);
    float sy = __shfl_up_sync(0xFFFFFFFF, x.y, 1);
    float2 v = (lane == 0) ? make_float2(0.f, 0.f) : make_float2(sx, sy);

    float2* pr = (float2*)g_prefT;
#pragma unroll
    for (int e = 0; e < 8; e++) {
        v = make_float2(fmaf(M.x, v.x, fmaf(-M.y, v.y, cb[e].x)),
                        fmaf(M.x, v.y, fmaf( M.y, v.x, cb[e].y)));
        pr[(lane * 8 + e) * NPAIR + p] = v;
    }
}

// ============================================================
// scan3: block c handles rows [c*16, c*16+16); thread p = pair.
// ============================================================
__global__ __launch_bounds__(256, 1) void scan3() {
    int c = blockIdx.x;        // 0..255
    int p = threadIdx.x;       // 0..255

    float g  = g_pair[p*8 + 0];
    float gc = g * g_pair[p*8 + 1];
    float gs = g * g_pair[p*8 + 2];

    float a = 0.f, b = 0.f;
    if (c > 0) {
        float2 s = ldg64((const float2*)g_prefT + (c - 1) * NPAIR + p);
        a = s.x; b = s.y;
    }

    const float2* up = (const float2*)(g_U + (size_t)(c * CHUNK) * NCH) + p;
    __nv_bfloat162* yh = (__nv_bfloat162*)(g_Yh + (size_t)(c * CHUNK) * NCH) + p;
    __nv_bfloat162* yl = (__nv_bfloat162*)(g_Yl + (size_t)(c * CHUNK) * NCH) + p;

    float2 ub[8];
#pragma unroll
    for (int base = 0; base < CHUNK; base += 8) {
#pragma unroll
        for (int e = 0; e < 8; e++) ub[e] = ldg64(up + (base + e) * 256);
#pragma unroll
        for (int e = 0; e < 8; e++) {
            float na = fmaf(gc, a, fmaf(-gs, b, ub[e].x));
            float nb = fmaf(gs, a, fmaf( gc, b, ub[e].y));
            a = na; b = nb;
            __nv_bfloat16 ha, la, hb, lb;
            bf16_split(a, ha, la);
            bf16_split(b, hb, lb);
            yh[(base + e) * 256] = __nv_bfloat162(ha, hb);
            yl[(base + e) * 256] = __nv_bfloat162(la, lb);
        }
    }
}

// ============================================================
extern "C" void kernel_launch(void* const* d_in, const int* in_sizes, int n_in,
                              void* d_out, int out_size) {
    const float* X         = (const float*)d_in[0];
    const float* theta_log = (const float*)d_in[1];
    const float* P         = (const float*)d_in[2];
    const float* Bmat      = (const float*)d_in[3];
    const float* Cmat      = (const float*)d_in[4];
    const float* Dv        = (const float*)d_in[5];
    const float* gamma_log = (const float*)d_in[6];
    float* out = (float*)d_out;

    const int GEMM_SMEM = NSTAGE * STAGEB;   // 163840
    cudaFuncSetAttribute(gemm_mma<0>, cudaFuncAttributeMaxDynamicSharedMemorySize, GEMM_SMEM);
    cudaFuncSetAttribute(gemm_mma<1>, cudaFuncAttributeMaxDynamicSharedMemorySize, GEMM_SMEM);

    setup<<<NHEAD, 256>>>(theta_log, P, gamma_log, Bmat, Cmat);
    prep<<<2048, 256>>>(X);

    float* U;   cudaGetSymbolAddress((void**)&U, g_U);
    __nv_bfloat16 *XTh, *XTl, *W1h, *W1l, *Yh, *Yl, *Ch, *Cl;
    cudaGetSymbolAddress((void**)&XTh, g_XTh);
    cudaGetSymbolAddress((void**)&XTl, g_XTl);
    cudaGetSymbolAddress((void**)&W1h, g_W1h);
    cudaGetSymbolAddress((void**)&W1l, g_W1l);
    cudaGetSymbolAddress((void**)&Yh, g_Yh);
    cudaGetSymbolAddress((void**)&Yl, g_Yl);
    cudaGetSymbolAddress((void**)&Ch, g_Ch);
    cudaGetSymbolAddress((void**)&Cl, g_Cl);

    dim3 gg(TSEQ / 128, NCH / 128);   // (32, 4)
    gemm_mma<0><<<gg, 256, GEMM_SMEM>>>(XTh, XTl, W1h, W1l, U, nullptr, nullptr, nullptr);
    kscan<<<64, 128>>>();
    scan3<<<NCHUNK, 256>>>();
    gemm_mma<1><<<gg, 256, GEMM_SMEM>>>(Yh, Yl, Ch, Cl, out, XTh, XTl, Dv);
}